// round 17
// baseline (speedup 1.0000x reference)
#include <cuda_runtime.h>
#include <cuda_fp16.h>
#include <math.h>

#define NB   2
#define NS   4096
#define NE   2560
#define NH   8
#define NKV  4
#define ND   256
#define NWIN 1024

// ---------------- scratch (device globals: allocation-free) ----------------
static __device__ __half g_qkvh[(size_t)NB * NS * (NH + 2 * NKV) * ND]; // fp16
static __device__ __half g_q  [(size_t)NB * NH  * NS * ND];             // fp16
static __device__ __half g_k  [(size_t)NB * NKV * NS * ND];
static __device__ __half g_v  [(size_t)NB * NKV * NS * ND];
static __device__ __half g_att[(size_t)NB * NS * NH * ND];              // fp16
static __device__ __half g_hh [(size_t)NB * NS * NE];                   // hidden fp16
static __device__ __half g_wq [(size_t)(NH + 2 * NKV) * ND * NE];       // w_qkv fp16
static __device__ __half g_wo [(size_t)NE * NH * ND];                   // w_o fp16

__device__ __forceinline__ unsigned h2u(float x, float y) {
    __half2 h = __floats2half2_rn(x, y);
    return *reinterpret_cast<unsigned*>(&h);
}

__device__ __forceinline__ float fast_tanh(float x) {
    float y;
    asm("tanh.approx.f32 %0, %1;" : "=f"(y) : "f"(x));
    return y;
}

__device__ __forceinline__ void mma_f16(float* d,
        unsigned a0, unsigned a1, unsigned a2, unsigned a3,
        unsigned b0, unsigned b1) {
    asm volatile(
        "mma.sync.aligned.m16n8k16.row.col.f32.f16.f16.f32 "
        "{%0,%1,%2,%3},{%4,%5,%6,%7},{%8,%9},{%0,%1,%2,%3};"
        : "+f"(d[0]), "+f"(d[1]), "+f"(d[2]), "+f"(d[3])
        : "r"(a0), "r"(a1), "r"(a2), "r"(a3), "r"(b0), "r"(b1));
}

__device__ __forceinline__ void ldsm4(unsigned& r0, unsigned& r1,
                                      unsigned& r2, unsigned& r3, unsigned a) {
    asm volatile("ldmatrix.sync.aligned.m8n8.x4.shared.b16 {%0,%1,%2,%3}, [%4];"
                 : "=r"(r0), "=r"(r1), "=r"(r2), "=r"(r3) : "r"(a));
}
__device__ __forceinline__ void ldsm4t(unsigned& r0, unsigned& r1,
                                       unsigned& r2, unsigned& r3, unsigned a) {
    asm volatile("ldmatrix.sync.aligned.m8n8.x4.trans.shared.b16 {%0,%1,%2,%3}, [%4];"
                 : "=r"(r0), "=r"(r1), "=r"(r2), "=r"(r3) : "r"(a));
}
__device__ __forceinline__ void cp16(unsigned smem_addr, const void* gptr) {
    asm volatile("cp.async.cg.shared.global [%0], [%1], 16;"
                 :: "r"(smem_addr), "l"(gptr));
}

// ---------------------------------------------------------------------------
// f32 -> f16 bulk convert, all three tensors in ONE launch
// ---------------------------------------------------------------------------
__global__ __launch_bounds__(256) void f2h3_kernel(
        const float* __restrict__ s0, __half* __restrict__ d0, int n0,
        const float* __restrict__ s1, __half* __restrict__ d1, int n1,
        const float* __restrict__ s2, __half* __restrict__ d2, int n2)
{
    int j = blockIdx.x * blockDim.x + threadIdx.x;
    const float* s; __half* d;
    if (j < n0) { s = s0; d = d0; }
    else if ((j -= n0) < n1) { s = s1; d = d1; }
    else if ((j -= n1) < n2) { s = s2; d = d2; }
    else return;
    float4 v = ((const float4*)s)[j];
    uint2 u;
    u.x = h2u(v.x, v.y);
    u.y = h2u(v.z, v.w);
    ((uint2*)d)[j] = u;
}

// ---------------------------------------------------------------------------
// Pure-fp16 tensor GEMM (round-13 proven config, byte-identical):
// 128x128 tile, BK=64, 256 threads (8 warps, 64x32), m16n8k16 + ldmatrix,
// 3-stage cp.async pipeline (one barrier per iter), 2 blocks/SM.
// ---------------------------------------------------------------------------
#define GP 36                 // smem pitch in uints; 36 % 32 == 4
#define ABUF (128 * GP)       // one operand buffer (uints)
#define STG  (2 * ABUF)       // one stage (A+B) in uints

template<typename TC>
__global__ __launch_bounds__(256, 2) void hgemm_nt(
        const __half* __restrict__ A, const __half* __restrict__ Bm,
        TC* __restrict__ C, int M, int N, int K)
{
    extern __shared__ unsigned gsm[];   // [3][STG]

    int tid  = threadIdx.x;
    int lane = tid & 31;
    int warp = tid >> 5;
    int wm = (warp & 1) * 64;
    int wn = (warp >> 1) * 32;

    const __half* Ab = A  + (size_t)blockIdx.y * 128 * K;
    const __half* Bb = Bm + (size_t)blockIdx.x * 128 * K;

    int lrow = tid >> 3;
    int lch  = tid & 7;
    unsigned smb = (unsigned)__cvta_generic_to_shared(gsm);
    unsigned aSt = smb + ((lrow * GP + lch * 4) << 2);
    unsigned bSt = aSt + ABUF * 4;

    float acc[16][4];
#pragma unroll
    for (int t = 0; t < 16; t++)
#pragma unroll
        for (int e = 0; e < 4; e++) acc[t][e] = 0.0f;

    int fr = lane >> 2;
    int r8 = lane & 7, quad = lane >> 3;
    unsigned aOff = smb + (((wm + (quad & 1) * 8 + r8) * GP + (quad >> 1) * 4) << 2);
    unsigned bOff = smb + (ABUF << 2)
                  + (((wn + (quad >> 1) * 8 + r8) * GP + (quad & 1) * 4) << 2);

    int nIter = K >> 6;

    // prologue: stages 0 and 1
#pragma unroll
    for (int s = 0; s < 2; s++) {
        unsigned sb = s * (STG * 4);
        int k0 = s << 6;
#pragma unroll
        for (int i = 0; i < 4; i++) {
            size_t go = (size_t)(lrow + 32 * i) * K + k0 + lch * 8;
            cp16(aSt + sb + i * (32 * GP * 4), Ab + go);
            cp16(bSt + sb + i * (32 * GP * 4), Bb + go);
        }
        asm volatile("cp.async.commit_group;");
    }

    for (int it = 0; it < nIter; it++) {
        int buf = it % 3;
        if (it >= nIter - 1) asm volatile("cp.async.wait_group 0;");
        else                 asm volatile("cp.async.wait_group 1;");
        __syncthreads();   // stage `it` visible; slot (it+2)%3 free (read at it-1)

        if (it + 2 < nIter) {
            unsigned sb = ((it + 2) % 3) * (STG * 4);
            int k0n = (it + 2) << 6;
#pragma unroll
            for (int i = 0; i < 4; i++) {
                size_t go = (size_t)(lrow + 32 * i) * K + k0n + lch * 8;
                cp16(aSt + sb + i * (32 * GP * 4), Ab + go);
                cp16(bSt + sb + i * (32 * GP * 4), Bb + go);
            }
            asm volatile("cp.async.commit_group;");
        }

        unsigned bufo = buf * (STG * 4);
#pragma unroll
        for (int ks = 0; ks < 4; ks++) {
            unsigned kb = bufo + ks * 32;
            unsigned af[4][4], bf[4][2];
#pragma unroll
            for (int i = 0; i < 4; i++)
                ldsm4(af[i][0], af[i][1], af[i][2], af[i][3],
                      aOff + i * (16 * GP * 4) + kb);
            ldsm4(bf[0][0], bf[0][1], bf[1][0], bf[1][1], bOff + kb);
            ldsm4(bf[2][0], bf[2][1], bf[3][0], bf[3][1], bOff + 16 * GP * 4 + kb);
#pragma unroll
            for (int i = 0; i < 4; i++)
#pragma unroll
                for (int j = 0; j < 4; j++)
                    mma_f16(acc[i * 4 + j], af[i][0], af[i][1], af[i][2], af[i][3],
                            bf[j][0], bf[j][1]);
        }
    }

    int c2 = (lane & 3) * 2;
#pragma unroll
    for (int i = 0; i < 4; i++) {
        size_t row0 = (size_t)blockIdx.y * 128 + wm + i * 16 + fr;
#pragma unroll
        for (int j = 0; j < 4; j++) {
            float* d = acc[i * 4 + j];
            size_t col = (size_t)blockIdx.x * 128 + wn + j * 8 + c2;
            if (sizeof(TC) == 2) {
                *(unsigned*)&((__half*)C)[row0 * N + col]       = h2u(d[0], d[1]);
                *(unsigned*)&((__half*)C)[(row0 + 8) * N + col] = h2u(d[2], d[3]);
            } else {
                *(float2*)&((float*)C)[row0 * N + col]       = make_float2(d[0], d[1]);
                *(float2*)&((float*)C)[(row0 + 8) * N + col] = make_float2(d[2], d[3]);
            }
        }
    }
}

// ---------------------------------------------------------------------------
// RMSNorm + RoPE + scatter into fp16 q/k/v buffers (reads fp16 qkv).
// ---------------------------------------------------------------------------
__global__ __launch_bounds__(512) void norm_rope_kernel(
        const float* __restrict__ fcos, const float* __restrict__ fsin,
        const int*   __restrict__ kvidx,
        const float* __restrict__ qw, const float* __restrict__ kw)
{
    int token = blockIdx.x;
    int b = token / NS;
    int s = token - b * NS;
    int warp = threadIdx.x >> 5;
    int lane = threadIdx.x & 31;

    const __half* src = g_qkvh + (size_t)token * ((NH + 2 * NKV) * ND) + warp * ND;

    float x1[4], x2[4];
#pragma unroll
    for (int i = 0; i < 4; i++) {
        x1[i] = __half2float(src[lane + 32 * i]);
        x2[i] = __half2float(src[128 + lane + 32 * i]);
    }

    if (warp >= 12) { // V: copy
        int kh = warp - 12;
        __half* dst = g_v + ((size_t)(b * NKV + kh) * NS + kvidx[s]) * ND;
#pragma unroll
        for (int i = 0; i < 4; i++) {
            dst[lane + 32 * i]       = __float2half(x1[i]);
            dst[128 + lane + 32 * i] = __float2half(x2[i]);
        }
        return;
    }

    float ss = 0.0f;
#pragma unroll
    for (int i = 0; i < 4; i++) ss += x1[i] * x1[i] + x2[i] * x2[i];
#pragma unroll
    for (int m = 16; m; m >>= 1) ss += __shfl_xor_sync(0xffffffffu, ss, m);
    float inv = rsqrtf(ss * (1.0f / ND) + 1e-6f);

    const float* w   = (warp < 8) ? qw : kw;
    float scale      = (warp < 8) ? 0.0625f : 1.0f; // SCALING folded into q
    __half* dst;
    if (warp < 8) dst = g_q + ((size_t)(b * NH + warp) * NS + s) * ND;
    else          dst = g_k + ((size_t)(b * NKV + (warp - 8)) * NS + kvidx[s]) * ND;

#pragma unroll
    for (int i = 0; i < 4; i++) {
        int d = lane + 32 * i;
        float c  = fcos[(size_t)s * 128 + d];
        float sn = fsin[(size_t)s * 128 + d];
        float y1 = x1[i] * inv * (1.0f + w[d]);
        float y2 = x2[i] * inv * (1.0f + w[d + 128]);
        dst[d]       = __float2half((y1 * c - y2 * sn) * scale);
        dst[d + 128] = __float2half((y2 * c + y1 * sn) * scale);
    }
}

// ---------------------------------------------------------------------------
// Sliding-window flash attention, fp16 m16n8k16 + ldmatrix, 2 blocks/SM.
// Mask specialization: the sliding-causal mask binds only on the diagonal
// tile (kt==qt) and the window-boundary tile (kt==qt-16, qt>=16). All
// interior tiles skip the per-element index/compare/select chain entirely
// (block-uniform branch) — targets the 14.1% alu slice ncu showed.
// ---------------------------------------------------------------------------
#define QP2 132
#define VTP 36

__global__ __launch_bounds__(256, 2) void attn_mma_kernel()
{
    extern __shared__ unsigned smu[];
    unsigned* Qs = smu;                    // [64][QP2]
    unsigned* Ks = Qs + 64 * QP2;          // [64][QP2]
    unsigned* Vs = Ks + 64 * QP2;          // [64][QP2]
    unsigned* Pp = Vs + 64 * QP2;          // [64][VTP]
    float* pmax = (float*)(Pp + 64 * VTP); // [64][2]
    float* psum = pmax + 128;              // [64][2]
    float* ms   = psum + 128;              // [64]
    float* ls   = ms + 64;
    float* cs   = ls + 64;

    int qt = blockIdx.x, h = blockIdx.y, b = blockIdx.z;
    int q0 = qt * 64;
    int kh = h >> 1;

    const unsigned* Qg = (const unsigned*)(g_q + ((size_t)(b * NH + h) * NS + q0) * ND);
    const unsigned* Kg = (const unsigned*)(g_k + (size_t)(b * NKV + kh) * NS * ND);
    const unsigned* Vg = (const unsigned*)(g_v + (size_t)(b * NKV + kh) * NS * ND);

    int tid  = threadIdx.x;
    int lane = tid & 31;
    int warp = tid >> 5;
    int wr = warp & 3;
    int wc = warp >> 2;
    int fr = lane >> 2;
    int fc = lane & 3;
    int r8 = lane & 7, quad = lane >> 3;

    unsigned qsm = (unsigned)__cvta_generic_to_shared(Qs);
    unsigned ksm = (unsigned)__cvta_generic_to_shared(Ks);
    unsigned vsm = (unsigned)__cvta_generic_to_shared(Vs);
    unsigned psm = (unsigned)__cvta_generic_to_shared(Pp);

    unsigned qOff = qsm + (((16 * wr + (quad & 1) * 8 + r8) * QP2 + (quad >> 1) * 4) << 2);
    unsigned kOff = ksm + (((32 * wc + (quad >> 1) * 8 + r8) * QP2 + (quad & 1) * 4) << 2);
    unsigned pOff = psm + ((((quad & 1) * 8 + r8) * VTP + (quad >> 1) * 4) << 2);
    unsigned vOff = vsm + ((((quad & 1) * 8 + r8) * QP2 + 16 * warp + (quad >> 1) * 4) << 2);

    for (int i = tid; i < 64 * 32; i += 256) {
        int r = i >> 5, c4 = (i & 31) * 4;
        *(uint4*)&Qs[r * QP2 + c4] = *(const uint4*)(Qg + (size_t)r * 128 + c4);
    }
    if (tid < 64) { ms[tid] = -1e30f; ls[tid] = 0.0f; }

    float oacc[16][4];
#pragma unroll
    for (int t = 0; t < 16; t++)
#pragma unroll
        for (int e = 0; e < 4; e++) oacc[t][e] = 0.0f;

    int t0 = qt - 16; if (t0 < 0) t0 = 0;
    int r0 = 16 * wr + fr;

    for (int kt = t0; kt <= qt; kt++) {
        int k0 = kt * 64;
        bool needMask = (kt == qt) || (qt >= 16 && kt == t0);
        __syncthreads(); // A

        for (int i = tid; i < 64 * 32; i += 256) {
            int r = i >> 5, c4 = (i & 31) * 4;
            *(uint4*)&Ks[r * QP2 + c4] = *(const uint4*)(Kg + (size_t)(k0 + r) * 128 + c4);
            *(uint4*)&Vs[r * QP2 + c4] = *(const uint4*)(Vg + (size_t)(k0 + r) * 128 + c4);
        }
        __syncthreads(); // B

        float sacc[4][4];
#pragma unroll
        for (int t = 0; t < 4; t++)
#pragma unroll
            for (int e = 0; e < 4; e++) sacc[t][e] = 0.0f;

#pragma unroll
        for (int ks = 0; ks < 16; ks++) {
            unsigned kb = ks * 32;
            unsigned a0, a1, a2, a3;
            ldsm4(a0, a1, a2, a3, qOff + kb);
            unsigned bf[4][2];
            ldsm4(bf[0][0], bf[0][1], bf[1][0], bf[1][1], kOff + kb);
            ldsm4(bf[2][0], bf[2][1], bf[3][0], bf[3][1], kOff + 16 * QP2 * 4 + kb);
#pragma unroll
            for (int nt = 0; nt < 4; nt++)
                mma_f16(sacc[nt], a0, a1, a2, a3, bf[nt][0], bf[nt][1]);
        }

        float mx0 = -1e30f, mx1 = -1e30f;
        if (needMask) {
#pragma unroll
            for (int nt = 0; nt < 4; nt++) {
#pragma unroll
                for (int e = 0; e < 4; e++) {
                    int r  = r0 + (e >> 1) * 8;
                    int kj = k0 + 32 * wc + 8 * nt + 2 * fc + (e & 1);
                    int qi = q0 + r;
                    float v = 50.0f * fast_tanh(sacc[nt][e] * 0.02f);
                    bool ok = (kj <= qi) && (qi - kj < NWIN);
                    v = ok ? v : -1e30f;
                    sacc[nt][e] = v;
                    if ((e >> 1) == 0) mx0 = fmaxf(mx0, v); else mx1 = fmaxf(mx1, v);
                }
            }
        } else {
#pragma unroll
            for (int nt = 0; nt < 4; nt++) {
#pragma unroll
                for (int e = 0; e < 4; e++) {
                    float v = 50.0f * fast_tanh(sacc[nt][e] * 0.02f);
                    sacc[nt][e] = v;
                    if ((e >> 1) == 0) mx0 = fmaxf(mx0, v); else mx1 = fmaxf(mx1, v);
                }
            }
        }
        mx0 = fmaxf(mx0, __shfl_xor_sync(0xffffffffu, mx0, 1));
        mx0 = fmaxf(mx0, __shfl_xor_sync(0xffffffffu, mx0, 2));
        mx1 = fmaxf(mx1, __shfl_xor_sync(0xffffffffu, mx1, 1));
        mx1 = fmaxf(mx1, __shfl_xor_sync(0xffffffffu, mx1, 2));
        if (fc == 0) {
            pmax[r0 * 2 + wc]       = mx0;
            pmax[(r0 + 8) * 2 + wc] = mx1;
        }
        __syncthreads(); // C

        {
            float mo0 = ms[r0];
            float mo1 = ms[r0 + 8];
            float mn0 = fmaxf(mo0, fmaxf(pmax[r0 * 2], pmax[r0 * 2 + 1]));
            float mn1 = fmaxf(mo1, fmaxf(pmax[(r0 + 8) * 2], pmax[(r0 + 8) * 2 + 1]));
            if (wc == 0 && fc == 0) {
                cs[r0]     = __expf(mo0 - mn0);
                cs[r0 + 8] = __expf(mo1 - mn1);
                ms[r0]     = mn0;
                ms[r0 + 8] = mn1;
            }
            float rs0 = 0.0f, rs1 = 0.0f;
#pragma unroll
            for (int nt = 0; nt < 4; nt++) {
                float p0 = __expf(sacc[nt][0] - mn0);
                float p1 = __expf(sacc[nt][1] - mn0);
                float p2 = __expf(sacc[nt][2] - mn1);
                float p3 = __expf(sacc[nt][3] - mn1);
                rs0 += p0 + p1; rs1 += p2 + p3;
                int cu = 16 * wc + 4 * nt + fc;
                Pp[r0 * VTP + cu]       = h2u(p0, p1);
                Pp[(r0 + 8) * VTP + cu] = h2u(p2, p3);
            }
            rs0 += __shfl_xor_sync(0xffffffffu, rs0, 1);
            rs0 += __shfl_xor_sync(0xffffffffu, rs0, 2);
            rs1 += __shfl_xor_sync(0xffffffffu, rs1, 1);
            rs1 += __shfl_xor_sync(0xffffffffu, rs1, 2);
            if (fc == 0) {
                psum[r0 * 2 + wc]       = rs0;
                psum[(r0 + 8) * 2 + wc] = rs1;
            }
        }
        __syncthreads(); // D

        if (tid < 64)
            ls[tid] = ls[tid] * cs[tid] + psum[tid * 2] + psum[tid * 2 + 1];
        {
            float cr0[4], cr1[4];
#pragma unroll
            for (int mt = 0; mt < 4; mt++) {
                cr0[mt] = cs[16 * mt + fr];
                cr1[mt] = cs[16 * mt + fr + 8];
            }
#pragma unroll
            for (int mt = 0; mt < 4; mt++)
#pragma unroll
                for (int nt = 0; nt < 4; nt++) {
                    float* d = oacc[mt * 4 + nt];
                    d[0] *= cr0[mt]; d[1] *= cr0[mt];
                    d[2] *= cr1[mt]; d[3] *= cr1[mt];
                }
#pragma unroll
            for (int s = 0; s < 4; s++) {
                unsigned pa[4][4];
#pragma unroll
                for (int mt = 0; mt < 4; mt++)
                    ldsm4(pa[mt][0], pa[mt][1], pa[mt][2], pa[mt][3],
                          pOff + mt * (16 * VTP * 4) + s * 32);
                unsigned vb[4][2];
                ldsm4t(vb[0][0], vb[0][1], vb[1][0], vb[1][1],
                       vOff + s * (16 * QP2 * 4));
                ldsm4t(vb[2][0], vb[2][1], vb[3][0], vb[3][1],
                       vOff + s * (16 * QP2 * 4) + 32);
#pragma unroll
                for (int mt = 0; mt < 4; mt++)
#pragma unroll
                    for (int nt = 0; nt < 4; nt++)
                        mma_f16(oacc[mt * 4 + nt], pa[mt][0], pa[mt][1], pa[mt][2], pa[mt][3],
                                vb[nt][0], vb[nt][1]);
            }
        }
    }
    __syncthreads();

    {
        unsigned* Og = (unsigned*)(g_att + ((size_t)b * NS + q0) * (NH * ND) + h * ND);
#pragma unroll
        for (int mt = 0; mt < 4; mt++) {
            int r = 16 * mt + fr;
            float il0 = 1.0f / ls[r];
            float il1 = 1.0f / ls[r + 8];
#pragma unroll
            for (int nt = 0; nt < 4; nt++) {
                float* d = oacc[mt * 4 + nt];
                int cu = 16 * warp + 4 * nt + fc;
                Og[(size_t)r * 1024 + cu]       = h2u(d[0] * il0, d[1] * il0);
                Og[(size_t)(r + 8) * 1024 + cu] = h2u(d[2] * il1, d[3] * il1);
            }
        }
    }
}

// ---------------------------------------------------------------------------
extern "C" void kernel_launch(void* const* d_in, const int* in_sizes, int n_in,
                              void* d_out, int out_size)
{
    const float* hidden = (const float*)d_in[0];
    const float* fcos   = (const float*)d_in[1];
    const float* fsin   = (const float*)d_in[2];
    const int*   kvidx  = (const int*)  d_in[3];
    const float* w_qkv  = (const float*)d_in[8];
    const float* w_o    = (const float*)d_in[9];
    const float* qnw    = (const float*)d_in[10];
    const float* knw    = (const float*)d_in[11];
    float* out = (float*)d_out;

    void* p;
    cudaGetSymbolAddress(&p, g_qkvh); __half* qkv_ptr = (__half*)p;
    cudaGetSymbolAddress(&p, g_att);  __half* att_ptr = (__half*)p;
    cudaGetSymbolAddress(&p, g_hh);   __half* hh_ptr  = (__half*)p;
    cudaGetSymbolAddress(&p, g_wq);   __half* wq_ptr  = (__half*)p;
    cudaGetSymbolAddress(&p, g_wo);   __half* wo_ptr  = (__half*)p;

    // 0) convert hidden + both weights to fp16 (single launch)
    {
        int n0 = NB * NS * NE / 4;
        int n1 = (NH + 2 * NKV) * ND * NE / 4;
        int n2 = NE * NH * ND / 4;
        int nt = n0 + n1 + n2;
        f2h3_kernel<<<(nt + 255) / 256, 256>>>(hidden, hh_ptr, n0,
                                               w_qkv, wq_ptr, n1,
                                               w_o, wo_ptr, n2);
    }

    size_t gsmem = (size_t)3 * STG * 4; // 108 KB
    cudaFuncSetAttribute(hgemm_nt<__half>,
                         cudaFuncAttributeMaxDynamicSharedMemorySize, (int)gsmem);
    cudaFuncSetAttribute(hgemm_nt<float>,
                         cudaFuncAttributeMaxDynamicSharedMemorySize, (int)gsmem);

    // 1) QKV projection (fp16 in, fp16 out)
    {
        dim3 grid((NH + 2 * NKV) * ND / 128, NB * NS / 128);
        hgemm_nt<__half><<<grid, 256, gsmem>>>(hh_ptr, wq_ptr, qkv_ptr,
                                               NB * NS, (NH + 2 * NKV) * ND, NE);
    }

    // 2) RMSNorm + RoPE + cache scatter (fp16 in/out)
    norm_rope_kernel<<<NB * NS, 512>>>(fcos, fsin, kvidx, qnw, knw);

    // 3) sliding-window flash attention (mask-specialized)
    {
        size_t smem = (size_t)(3 * 64 * QP2 + 64 * VTP + 448) * 4;
        cudaFuncSetAttribute(attn_mma_kernel,
                             cudaFuncAttributeMaxDynamicSharedMemorySize,
                             (int)smem);
        dim3 grid(NS / 64, NH, NB);
        attn_mma_kernel<<<grid, 256, smem>>>();
    }

    // 4) output projection (fp16 in, f32 out)
    {
        dim3 grid(NE / 128, NB * NS / 128);
        hgemm_nt<float><<<grid, 256, gsmem>>>(att_ptr, wo_ptr, out,
                                              NB * NS, NE, NH * ND);
    }
}